// round 5
// baseline (speedup 1.0000x reference)
#include <cuda_runtime.h>
#include <math_constants.h>

// Problem shapes (fixed by the dataset instance)
#define NVARS_MAX 2000000
#define N0_MAX    4000000
#define N1_MAX    2000000
#define N2_MAX    1000000

// Scratch: intermediates live in device globals (no allocation allowed).
// g_x  : encoded input  [2 + 2*n_vars]  = 16 MB
// g_b0 : layer0 output  [n0]            = 16 MB
// g_b1 : layer1 output  [n1]            =  8 MB
// g_b2 : layer2 output  [n2]            =  4 MB
__device__ float g_x [2 + 2 * NVARS_MAX];
__device__ float g_b0[N0_MAX];
__device__ float g_b1[N1_MAX];
__device__ float g_b2[N2_MAX];

// ---------------------------------------------------------------------------
// Encode: x[0] = -inf, x[1] = 0, x[2+2i] = w[i], x[3+2i] = log1mexp(w[i])
// log1mexp(x) = log(-expm1(x))  for x > -log2   (accurate near 0)
//             = log1p(-exp(x))  otherwise
// ---------------------------------------------------------------------------
__global__ void encode_kernel(const float* __restrict__ w, float* __restrict__ x, int n)
{
    int i = blockIdx.x * blockDim.x + threadIdx.x;
    if (i >= n) return;
    float p = w[i];
    float neg;
    if (p > -0.69314718056f) {
        neg = __logf(-expm1f(p));
    } else {
        neg = log1pf(-__expf(p));
    }
    // interleaved [pos, neg] starting at x+2; 8-byte aligned float2 store
    reinterpret_cast<float2*>(x + 2)[i] = make_float2(p, neg);
    if (i == 0) {
        x[0] = -CUDART_INF_F;
        x[1] = 0.0f;
    }
}

// ---------------------------------------------------------------------------
// Product layer (log semiring): out[j] = sum of 4 gathered values.
// csr is repeat(arange(n),4) -> segment j reads ptrs[4j..4j+3] = one int4.
// ---------------------------------------------------------------------------
__global__ void sum_kernel(const float* __restrict__ x,
                           const int4*  __restrict__ ptrs,
                           float*       __restrict__ out, int n)
{
    int j = blockIdx.x * blockDim.x + threadIdx.x;
    if (j >= n) return;
    int4 p = ptrs[j];
    float a = __ldg(x + p.x);
    float b = __ldg(x + p.y);
    float c = __ldg(x + p.z);
    float d = __ldg(x + p.w);
    out[j] = (a + b) + (c + d);   // -inf propagates correctly, no NaN possible
}

// ---------------------------------------------------------------------------
// Sum layer (log semiring): numerically stable 4-way log-sum-exp + eps.
// If m == -inf then all 4 inputs are -inf; reference yields log(4+eps)+(-inf)
// == -inf, so emit -inf directly. __expf(-inf) == 0 covers mixed cases.
// ---------------------------------------------------------------------------
__global__ void lse_kernel(const float* __restrict__ x,
                           const int4*  __restrict__ ptrs,
                           float*       __restrict__ out, int n)
{
    int j = blockIdx.x * blockDim.x + threadIdx.x;
    if (j >= n) return;
    int4 p = ptrs[j];
    float a = __ldg(x + p.x);
    float b = __ldg(x + p.y);
    float c = __ldg(x + p.z);
    float d = __ldg(x + p.w);
    float m = fmaxf(fmaxf(a, b), fmaxf(c, d));
    float r;
    if (m == -CUDART_INF_F) {
        r = -CUDART_INF_F;
    } else {
        float s = __expf(a - m) + __expf(b - m) + __expf(c - m) + __expf(d - m) + 1e-15f;
        r = __logf(s) + m;
    }
    out[j] = r;
}

extern "C" void kernel_launch(void* const* d_in, const int* in_sizes, int n_in,
                              void* d_out, int out_size)
{
    // metadata order (setup_inputs dict order):
    //   0:weights 1:ptrs0 2:csr0 3:n0 4:ptrs1 5:csr1 6:n1
    //   7:ptrs2 8:csr2 9:n2 10:ptrs3 11:csr3 12:n3
    // Fallback: if the scalars n{i} are NOT passed as inputs (n_in == 9),
    // layout is 0:weights 1:ptrs0 2:csr0 3:ptrs1 4:csr1 5:ptrs2 6:csr2 7:ptrs3 8:csr3.
    int i0, i1, i2, i3;
    if (n_in >= 13) { i0 = 1; i1 = 4; i2 = 7; i3 = 10; }
    else            { i0 = 1; i1 = 3; i2 = 5; i3 = 7;  }

    const float* w  = (const float*)d_in[0];
    const int4*  p0 = (const int4*) d_in[i0];
    const int4*  p1 = (const int4*) d_in[i1];
    const int4*  p2 = (const int4*) d_in[i2];
    const int4*  p3 = (const int4*) d_in[i3];

    int n_vars = in_sizes[0];
    int n0 = in_sizes[i0] / 4;
    int n1 = in_sizes[i1] / 4;
    int n2 = in_sizes[i2] / 4;
    int n3 = in_sizes[i3] / 4;   // == out_size

    float *x, *b0, *b1, *b2;
    cudaGetSymbolAddress((void**)&x,  g_x);
    cudaGetSymbolAddress((void**)&b0, g_b0);
    cudaGetSymbolAddress((void**)&b1, g_b1);
    cudaGetSymbolAddress((void**)&b2, g_b2);

    const int T = 256;
    encode_kernel<<<(n_vars + T - 1) / T, T>>>(w, x, n_vars);
    sum_kernel  <<<(n0 + T - 1) / T, T>>>(x,  p0, b0, n0);
    lse_kernel  <<<(n1 + T - 1) / T, T>>>(b0, p1, b1, n1);
    sum_kernel  <<<(n2 + T - 1) / T, T>>>(b1, p2, b2, n2);
    lse_kernel  <<<(n3 + T - 1) / T, T>>>(b2, p3, (float*)d_out, n3);
}